// round 1
// baseline (speedup 1.0000x reference)
#include <cuda_runtime.h>
#include <cuda_bf16.h>
#include <math.h>

#define NB 8
#define BATCH 256
#define NV 14062
#define NV3 (NV*3)
#define KDIM 128
#define BM 64      // batches per block tile
#define BV 32      // vertices per block tile
#define KC 64      // k-chunk held in shared

// scratch (allocation-free requirement -> device globals)
__device__ float g_coef[BATCH * KDIM];      // [b][k] coefficient vectors
__device__ float g_bone[BATCH * NB * 12];   // [b][n][3x4 row-major]

struct Aff { float r[9]; float t[3]; };

__device__ __forceinline__ Aff amul(const Aff& A, const Aff& B) {
    Aff C;
#pragma unroll
    for (int i = 0; i < 3; i++) {
#pragma unroll
        for (int j = 0; j < 3; j++) {
            C.r[i*3+j] = A.r[i*3+0]*B.r[0*3+j] + A.r[i*3+1]*B.r[1*3+j] + A.r[i*3+2]*B.r[2*3+j];
        }
        C.t[i] = A.r[i*3+0]*B.t[0] + A.r[i*3+1]*B.t[1] + A.r[i*3+2]*B.t[2] + A.t[i];
    }
    return C;
}

__device__ __forceinline__ Aff ainv_rigid(const Aff& A) {
    Aff C;
#pragma unroll
    for (int i = 0; i < 3; i++)
#pragma unroll
        for (int j = 0; j < 3; j++)
            C.r[i*3+j] = A.r[j*3+i];
#pragma unroll
    for (int i = 0; i < 3; i++)
        C.t[i] = -(C.r[i*3+0]*A.t[0] + C.r[i*3+1]*A.t[1] + C.r[i*3+2]*A.t[2]);
    return C;
}

__device__ __forceinline__ void rodrigues(const float* rv, float* R) {
    float x = rv[0], y = rv[1], z = rv[2];
    float d = x*x + y*y + z*z + 1e-12f;
    float ang = sqrtf(d);
    float inv = 1.0f / ang;
    float kx = x*inv, ky = y*inv, kz = z*inv;
    float s = sinf(ang), c = cosf(ang);
    float kk = kx*kx + ky*ky + kz*kz;   // match reference's literal K@K
    float oc = 1.0f - c;
    R[0] = 1.0f + oc*(kx*kx - kk);
    R[1] = -s*kz + oc*(kx*ky);
    R[2] =  s*ky + oc*(kx*kz);
    R[3] =  s*kz + oc*(ky*kx);
    R[4] = 1.0f + oc*(ky*ky - kk);
    R[5] = -s*kx + oc*(ky*kz);
    R[6] = -s*ky + oc*(kz*kx);
    R[7] =  s*kx + oc*(kz*ky);
    R[8] = 1.0f + oc*(kz*kz - kk);
}

// One thread per batch: Rodrigues + FK chain + inverse binds + coef vector.
__global__ void prep_kernel(const float* __restrict__ theta,
                            const float* __restrict__ bsw,
                            const float* __restrict__ L2P) {
    int b = threadIdx.x;
    if (b >= BATCH) return;

    float R[NB][9];
#pragma unroll
    for (int n = 0; n < NB; n++)
        rodrigues(theta + (b*NB + n)*3, R[n]);

    float* c = g_coef + b*KDIM;
    // bone 0: theta_zero = R0 - R0 = 0
#pragma unroll
    for (int j = 0; j < 9; j++) c[j] = 0.0f;
#pragma unroll
    for (int n = 1; n < NB; n++)
#pragma unroll
        for (int i = 0; i < 3; i++)
#pragma unroll
            for (int j = 0; j < 3; j++)
                c[n*9 + i*3 + j] = R[n][i*3+j] - (i == j ? 1.0f : 0.0f);
    for (int j = 0; j < 55; j++) c[72 + j] = bsw[b*55 + j];
    c[127] = 1.0f;

    Aff M, rest;
#pragma unroll
    for (int n = 0; n < NB; n++) {
        Aff l2p;
#pragma unroll
        for (int i = 0; i < 3; i++) {
#pragma unroll
            for (int j = 0; j < 3; j++) l2p.r[i*3+j] = L2P[n*16 + i*4 + j];
            l2p.t[i] = L2P[n*16 + i*4 + 3];
        }
        Aff loc;
#pragma unroll
        for (int i = 0; i < 9; i++) loc.r[i] = R[n][i];
        loc.t[0] = loc.t[1] = loc.t[2] = 0.0f;

        Aff An = amul(l2p, loc);
        M    = (n == 0) ? An  : amul(M, An);
        rest = (n == 0) ? l2p : amul(rest, l2p);

        Aff w2l = ainv_rigid(rest);
        Aff G = amul(M, w2l);

        float* g = g_bone + b*(NB*12) + n*12;
#pragma unroll
        for (int i = 0; i < 3; i++) {
            g[i*4+0] = G.r[i*3+0];
            g[i*4+1] = G.r[i*3+1];
            g[i*4+2] = G.r[i*3+2];
            g[i*4+3] = G.t[i];
        }
    }
}

// Main: [BM batches x BV vertices] tile. GEMM over K=128 + fused epilogue
// (larynx bilinear sample + linear blend skinning).
__global__ __launch_bounds__(256, 2)
void hack_main_kernel(const float* __restrict__ P,
                      const float* __restrict__ E,
                      const float* __restrict__ T,
                      const float* __restrict__ W,
                      const float* __restrict__ ts,
                      const float* __restrict__ uvgrid,
                      const float* __restrict__ L,
                      const float* __restrict__ tau,
                      const float* __restrict__ alpha,
                      float* __restrict__ out) {
    __shared__ float sA[KC * 65];   // [k][batch], pad 65 (conflict-free transpose)
    __shared__ float sB[KC * 96];   // [k][vertex-component], 96 = BV*3

    const int v0 = blockIdx.x * BV;
    const int b0 = blockIdx.y * BM;
    const int tid = threadIdx.x;
    const int tcol = tid & 15;   // vertex-pair group (2 vertices)
    const int trow = tid >> 4;   // batch-quad group (4 batches)

    float acc[4][6];
#pragma unroll
    for (int m = 0; m < 4; m++)
#pragma unroll
        for (int q = 0; q < 6; q++) acc[m][q] = 0.0f;

#pragma unroll
    for (int kc = 0; kc < KDIM / KC; kc++) {
        const int kbase = kc * KC;
        // load coef tile (transposed, coalesced reads)
        for (int i = tid; i < KC * BM; i += 256) {
            int bb = i >> 6;      // / KC
            int k  = i & (KC-1);  // % KC
            sA[k*65 + bb] = g_coef[(b0 + bb)*KDIM + kbase + k];
        }
        // load basis tile from P / E / T
        for (int i = tid; i < KC * 96; i += 256) {
            int kl  = i / 96;
            int col = i - kl*96;
            int k   = kbase + kl;
            int v   = v0 + col/3;
            int kk  = col - (col/3)*3;
            float val = 0.0f;
            if (v < NV) {
                if (k < 72)       val = P[k*NV3 + v*3 + kk];
                else if (k < 127) val = E[(k-72)*NV3 + v*3 + kk];
                else              val = T[v*3 + kk];
            }
            sB[kl*96 + col] = val;
        }
        __syncthreads();

#pragma unroll 4
        for (int k = 0; k < KC; k++) {
            float a0 = sA[k*65 + trow*4 + 0];
            float a1 = sA[k*65 + trow*4 + 1];
            float a2 = sA[k*65 + trow*4 + 2];
            float a3 = sA[k*65 + trow*4 + 3];
            float bv[6];
#pragma unroll
            for (int q = 0; q < 6; q++) bv[q] = sB[k*96 + tcol*6 + q];
#pragma unroll
            for (int q = 0; q < 6; q++) {
                acc[0][q] = fmaf(a0, bv[q], acc[0][q]);
                acc[1][q] = fmaf(a1, bv[q], acc[1][q]);
                acc[2][q] = fmaf(a2, bv[q], acc[2][q]);
                acc[3][q] = fmaf(a3, bv[q], acc[3][q]);
            }
        }
        __syncthreads();
    }

    // Epilogue: L_tau*alpha + skinning
#pragma unroll
    for (int vv = 0; vv < 2; vv++) {
        const int v = v0 + tcol*2 + vv;
        if (v >= NV) continue;
        float w8[NB];
#pragma unroll
        for (int n = 0; n < NB; n++) w8[n] = W[n*NV + v];
        const float tsx = ts[v*3+0], tsy = ts[v*3+1], tsz = ts[v*3+2];
        const float ux = uvgrid[v*2+0], uy = uvgrid[v*2+1];

#pragma unroll
        for (int m = 0; m < 4; m++) {
            const int b = b0 + trow*4 + m;
            const float al = alpha[b];
            const float tb = tau[b];

            // bilinear sample of L (256x256), align_corners=True, border clamp
            float x = fminf(fmaxf(ux * 255.0f, 0.0f), 255.0f);
            float y = fminf(fmaxf((uy + tb) * 255.0f, 0.0f), 255.0f);
            int x0 = (int)floorf(x), y0 = (int)floorf(y);
            int x1 = min(x0 + 1, 255), y1 = min(y0 + 1, 255);
            float wx = x - (float)x0, wy = y - (float)y0;
            float v00 = L[y0*256 + x0], v01 = L[y0*256 + x1];
            float v10 = L[y1*256 + x0], v11 = L[y1*256 + x1];
            float dist = (v00*(1.0f-wx) + v01*wx)*(1.0f-wy)
                       + (v10*(1.0f-wx) + v11*wx)*wy;
            float s = al * dist;

            float px = acc[m][vv*3+0] + s*tsx;
            float py = acc[m][vv*3+1] + s*tsy;
            float pz = acc[m][vv*3+2] + s*tsz;

            const float4* Gb = (const float4*)(g_bone + b*(NB*12));
            float ox = 0.0f, oy = 0.0f, oz = 0.0f;
#pragma unroll
            for (int n = 0; n < NB; n++) {
                float4 r0 = Gb[n*3 + 0];
                float4 r1 = Gb[n*3 + 1];
                float4 r2 = Gb[n*3 + 2];
                float w = w8[n];
                ox = fmaf(w, fmaf(r0.x, px, fmaf(r0.y, py, fmaf(r0.z, pz, r0.w))), ox);
                oy = fmaf(w, fmaf(r1.x, px, fmaf(r1.y, py, fmaf(r1.z, pz, r1.w))), oy);
                oz = fmaf(w, fmaf(r2.x, px, fmaf(r2.y, py, fmaf(r2.z, pz, r2.w))), oz);
            }
            long base = (long)b * NV3 + (long)v * 3;
            out[base + 0] = ox;
            out[base + 1] = oy;
            out[base + 2] = oz;
        }
    }
}

extern "C" void kernel_launch(void* const* d_in, const int* in_sizes, int n_in,
                              void* d_out, int out_size) {
    const float* theta  = (const float*)d_in[0];
    const float* tau    = (const float*)d_in[1];
    const float* alpha  = (const float*)d_in[2];
    const float* bsw    = (const float*)d_in[3];
    const float* W      = (const float*)d_in[4];
    const float* T      = (const float*)d_in[5];
    const float* P      = (const float*)d_in[6];
    const float* L      = (const float*)d_in[7];
    const float* ts     = (const float*)d_in[8];
    const float* L2P    = (const float*)d_in[9];
    const float* E      = (const float*)d_in[10];
    const float* uvgrid = (const float*)d_in[11];
    float* out = (float*)d_out;

    prep_kernel<<<1, 256>>>(theta, bsw, L2P);

    dim3 grid((NV + BV - 1) / BV, BATCH / BM);
    hack_main_kernel<<<grid, 256>>>(P, E, T, W, ts, uvgrid, L, tau, alpha, out);
}